// round 2
// baseline (speedup 1.0000x reference)
#include <cuda_runtime.h>
#include <cstdint>

#define Bb 4
#define Nn 2048
#define Cc 256
#define OO 256
#define Ss 32
#define BP (Bb*Nn)            // 8192
#define Ee (BP*Ss)            // 262144
#define K1 259

#define HMINf (-0.02f)
#define HMAXf (0.04f)
#define EPSf  (1e-5f)
#define INVCNT (1.0f/(float)Ee)

// ---------------- static device scratch (allocation-free rule) ----------------
__device__ float d_W1fT[Cc*OO];            // W1fT[c][o] = W1[o][3+c]
__device__ float d_W2T [OO*OO];            // W2T[c][o]  = W2[o][c]
__device__ int   d_idx [BP*Ss];            // neighbor indices
__device__ float d_F1  [(size_t)Bb*Nn*OO]; // F1[b][n][o] = (W1_feat @ feat[b])[o,n]  (8MB)
__device__ float d_y2  [(size_t)Ee*OO];    // conv2 pre-norm output, [e][o]           (256MB)
__device__ float d_ps1s[BP*OO], d_ps1q[BP*OO];   // per-(b,p) partial sums, stage 1
__device__ float d_ps2s[BP*OO], d_ps2q[BP*OO];   // stage 2
__device__ float d_pp  [4*32*OO];                // level-2 partials
__device__ float d_scale1[OO], d_shift1[OO];
__device__ float d_scale2[OO], d_shift2[OO];

// ---------------- K0: weight transposes ----------------
__global__ void k_wt(const float* __restrict__ W1, const float* __restrict__ W2){
    int i = blockIdx.x*256 + threadIdx.x;      // 0..65535, i = c*256 + o
    int c = i >> 8, o = i & 255;
    d_W1fT[i] = W1[o*K1 + 3 + c];
    d_W2T[i]  = W2[o*OO + c];
}

// ---------------- K1: cylinder query (one warp per (b,p)) ----------------
__global__ void k_idx(const float* __restrict__ xyz, const float* __restrict__ rot){
    int bp   = blockIdx.x*8 + (threadIdx.x >> 5);
    int lane = threadIdx.x & 31;
    int b = bp >> 11;
    const float* R = rot + (size_t)bp*9;
    float r00=R[0],r01=R[1],r02=R[2],r10=R[3],r11=R[4],r12=R[5],r20=R[6],r21=R[7],r22=R[8];
    const float* cc = xyz + (size_t)bp*3;
    float cx=cc[0], cy=cc[1], cz=cc[2];
    const float R2v = (float)(0.05*0.05);
    int count = 0, firstn = 0;
    bool have = false;
    for (int base = 0; base < Nn && count < Ss; base += 32){
        int n = base + lane;
        const float* q = xyz + ((size_t)b*Nn + n)*3;
        float dx=q[0]-cx, dy=q[1]-cy, dz=q[2]-cz;
        float a0 = r00*dx + r01*dy + r02*dz;
        float a1 = r10*dx + r11*dy + r12*dz;
        float a2 = r20*dx + r21*dy + r22*dz;
        bool m = (a1*a1 + a2*a2 < R2v) & (a0 > HMINf) & (a0 < HMAXf);
        unsigned bal = __ballot_sync(0xffffffffu, m);
        if (!have && bal){ firstn = base + (__ffs(bal) - 1); have = true; }
        int pre = __popc(bal & ((1u << lane) - 1u));
        if (m && count + pre < Ss) d_idx[bp*Ss + count + pre] = n;
        count += __popc(bal);
    }
    if (count < Ss){
        for (int j = count + lane; j < Ss; j += 32) d_idx[bp*Ss + j] = firstn;
    }
}

// ---------------- K2: F1 = W1_feat @ feat  (per-batch 256x256x2048 GEMM) ----------------
__global__ void __launch_bounds__(256) k_F1(const float* __restrict__ feat){
    int b  = blockIdx.y;
    int n0 = blockIdx.x * 32;
    __shared__ __align__(16) float fsh[32][32];   // [c-chunk][n]
    int tid = threadIdx.x;
    int o = tid;
    float acc[32];
    #pragma unroll
    for (int n = 0; n < 32; n++) acc[n] = 0.f;

    for (int ck = 0; ck < 8; ck++){
        // FIX (round 1): fill the full 32x32 tile — 1024 elements, 4 per thread
        #pragma unroll
        for (int r = 0; r < 4; r++){
            int li = tid + r*256;
            int ci = li >> 5, nj = li & 31;
            fsh[ci][nj] = feat[((size_t)b*Cc + ck*32 + ci)*Nn + n0 + nj];
        }
        __syncthreads();
        #pragma unroll 4
        for (int ci2 = 0; ci2 < 32; ci2++){
            float w = d_W1fT[(ck*32 + ci2)*OO + o];
            const float4* row = reinterpret_cast<const float4*>(&fsh[ci2][0]);
            #pragma unroll
            for (int nq = 0; nq < 8; nq++){
                float4 f = row[nq];
                acc[4*nq+0] = fmaf(f.x, w, acc[4*nq+0]);
                acc[4*nq+1] = fmaf(f.y, w, acc[4*nq+1]);
                acc[4*nq+2] = fmaf(f.z, w, acc[4*nq+2]);
                acc[4*nq+3] = fmaf(f.w, w, acc[4*nq+3]);
            }
        }
        __syncthreads();
    }
    #pragma unroll
    for (int n = 0; n < 32; n++)
        d_F1[((size_t)b*Nn + n0 + n)*OO + o] = acc[n];
}

// helper: build grouped xyz geometry for one (b,p) block (first 32 threads)
__device__ __forceinline__ void build_geom(const float* __restrict__ xyz,
                                           const float* __restrict__ rot,
                                           int bp, int b, int tid,
                                           int* idxs, float* gx, float* gy, float* gz){
    if (tid < 32){
        int s = tid;
        int i = d_idx[bp*Ss + s];
        idxs[s] = i;
        const float* R = rot + (size_t)bp*9;
        const float* c = xyz + (size_t)bp*3;
        const float* q = xyz + ((size_t)b*Nn + i)*3;
        float vx = (q[0]-c[0]) / 0.05f;
        float vy = (q[1]-c[1]) / 0.05f;
        float vz = (q[2]-c[2]) / 0.05f;
        // einsum('bpsj,bpjk->bpsk') : g_k = sum_j v_j * rot[j][k]
        gx[s] = vx*R[0] + vy*R[3] + vz*R[6];
        gy[s] = vx*R[1] + vy*R[4] + vz*R[7];
        gz[s] = vx*R[2] + vy*R[5] + vz*R[8];
    }
}

// ---------------- K3: stats of conv1 output (no materialization) ----------------
__global__ void __launch_bounds__(256) k_stats1(const float* __restrict__ xyz,
                                                const float* __restrict__ rot,
                                                const float* __restrict__ W1){
    int bp = blockIdx.x;
    int b = bp >> 11;
    __shared__ int   idxs[32];
    __shared__ float gx[32], gy[32], gz[32];
    int tid = threadIdx.x;
    build_geom(xyz, rot, bp, b, tid, idxs, gx, gy, gz);
    __syncthreads();

    int o = tid;
    float w0 = W1[o*K1+0], w1 = W1[o*K1+1], w2 = W1[o*K1+2];
    const float* F1b = d_F1 + (size_t)b*Nn*OO;
    float lsum = 0.f, lsq = 0.f;
    #pragma unroll 4
    for (int s = 0; s < Ss; s++){
        float v = F1b[(size_t)idxs[s]*OO + o];
        v = fmaf(w0, gx[s], fmaf(w1, gy[s], fmaf(w2, gz[s], v)));
        lsum += v;
        lsq  = fmaf(v, v, lsq);
    }
    d_ps1s[bp*OO + o] = lsum;
    d_ps1q[bp*OO + o] = lsq;
}

// ---------------- deterministic two-level reduction ----------------
__global__ void k_red_a(int base){
    int which = base + blockIdx.y;               // 0..3
    const float* src = (which == 0) ? d_ps1s : (which == 1) ? d_ps1q
                     : (which == 2) ? d_ps2s : d_ps2q;
    float* dst = d_pp + which*(32*OO);
    int z = blockIdx.x;                          // 0..31
    int o = threadIdx.x;
    float s = 0.f;
    for (int k = 0; k < 256; k++)
        s += src[((size_t)(z*256 + k))*OO + o];
    dst[z*OO + o] = s;
}

__global__ void k_red_b(int stage, const float* __restrict__ gamma,
                        const float* __restrict__ beta){
    int o = threadIdx.x;
    const float* pps = d_pp + (2*stage + 0)*(32*OO);
    const float* ppq = d_pp + (2*stage + 1)*(32*OO);
    float s = 0.f, q = 0.f;
    for (int z = 0; z < 32; z++){ s += pps[z*OO + o]; q += ppq[z*OO + o]; }
    float mu  = s * INVCNT;
    float var = q * INVCNT - mu*mu;
    float sc  = rsqrtf(var + EPSf) * gamma[o];
    float sf  = beta[o] - mu*sc;
    if (stage == 0){ d_scale1[o] = sc; d_shift1[o] = sf; }
    else           { d_scale2[o] = sc; d_shift2[o] = sf; }
}

// ---------------- K4: h1 = relu(BN(y1)) rebuilt on the fly; y2 = W2 @ h1; stats2 ----------------
__global__ void __launch_bounds__(256) k_conv2(const float* __restrict__ xyz,
                                               const float* __restrict__ rot,
                                               const float* __restrict__ W1){
    int bp = blockIdx.x;
    int b = bp >> 11;
    __shared__ int   idxs[32];
    __shared__ float gx[32], gy[32], gz[32];
    __shared__ __align__(16) float h_sh[32][260];   // [s][c], padded row
    int tid = threadIdx.x;
    build_geom(xyz, rot, bp, b, tid, idxs, gx, gy, gz);
    __syncthreads();

    // build h tile
    {
        int c = tid;
        float w0 = W1[c*K1+0], w1 = W1[c*K1+1], w2 = W1[c*K1+2];
        float sc = d_scale1[c], sf = d_shift1[c];
        const float* F1b = d_F1 + (size_t)b*Nn*OO;
        #pragma unroll 4
        for (int s = 0; s < Ss; s++){
            float v = F1b[(size_t)idxs[s]*OO + c];
            v = fmaf(w0, gx[s], fmaf(w1, gy[s], fmaf(w2, gz[s], v)));
            h_sh[s][c] = fmaxf(fmaf(v, sc, sf), 0.f);
        }
    }
    __syncthreads();

    // GEMM: y2[o] = sum_c W2[o][c] * h[c],  K = 256
    int o = tid;
    float acc[Ss];
    #pragma unroll
    for (int s = 0; s < Ss; s++) acc[s] = 0.f;

    #pragma unroll 1
    for (int c4 = 0; c4 < 64; c4++){
        float w0 = d_W2T[(c4*4+0)*OO + o];
        float w1 = d_W2T[(c4*4+1)*OO + o];
        float w2 = d_W2T[(c4*4+2)*OO + o];
        float w3 = d_W2T[(c4*4+3)*OO + o];
        #pragma unroll
        for (int s = 0; s < Ss; s++){
            float4 h4 = *reinterpret_cast<const float4*>(&h_sh[s][c4*4]);
            acc[s] = fmaf(h4.x, w0, acc[s]);
            acc[s] = fmaf(h4.y, w1, acc[s]);
            acc[s] = fmaf(h4.z, w2, acc[s]);
            acc[s] = fmaf(h4.w, w3, acc[s]);
        }
    }

    float* y = d_y2 + (size_t)bp*Ss*OO;
    float lsum = 0.f, lsq = 0.f;
    #pragma unroll
    for (int s = 0; s < Ss; s++){
        float v = acc[s];
        y[(size_t)s*OO + o] = v;
        lsum += v;
        lsq  = fmaf(v, v, lsq);
    }
    d_ps2s[bp*OO + o] = lsum;
    d_ps2q[bp*OO + o] = lsq;
}

// ---------------- K5: BN2 + relu + max over samples, transpose-write ----------------
__global__ void __launch_bounds__(256) k_final(float* __restrict__ out){
    int blk = blockIdx.x;                 // 256 blocks, 32 p's each
    int bp0 = blk * 32;
    int b = bp0 >> 11;
    int pbase = bp0 & 2047;
    int tid = threadIdx.x;
    __shared__ float sh[256*33];

    int o = tid;
    float sc = d_scale2[o], sf = d_shift2[o];
    for (int p = 0; p < 32; p++){
        const float* y = d_y2 + (size_t)(bp0 + p)*Ss*OO + o;
        float mm = 0.f;                   // relu floor: max(0, max_s v)
        #pragma unroll
        for (int s = 0; s < Ss; s++){
            float v = fmaf(y[(size_t)s*OO], sc, sf);
            mm = fmaxf(mm, v);
        }
        sh[o*33 + p] = mm;
    }
    __syncthreads();

    int p   = tid & 31;
    int og0 = (tid >> 5) * 32;
    #pragma unroll
    for (int k = 0; k < 32; k++){
        int o2 = og0 + k;
        out[((size_t)(b*OO + o2))*Nn + pbase + p] = sh[o2*33 + p];
    }
}

// ---------------- launcher ----------------
extern "C" void kernel_launch(void* const* d_in, const int* in_sizes, int n_in,
                              void* d_out, int out_size){
    (void)in_sizes; (void)n_in; (void)out_size;
    const float* xyz  = (const float*)d_in[0];
    const float* feat = (const float*)d_in[1];
    const float* rot  = (const float*)d_in[2];
    const float* W1   = (const float*)d_in[3];
    const float* g1   = (const float*)d_in[4];
    const float* b1   = (const float*)d_in[5];
    const float* W2   = (const float*)d_in[6];
    const float* g2   = (const float*)d_in[7];
    const float* b2   = (const float*)d_in[8];
    float* out = (float*)d_out;

    k_wt    <<<256, 256>>>(W1, W2);
    k_idx   <<<BP/8, 256>>>(xyz, rot);
    k_F1    <<<dim3(Nn/32, Bb), 256>>>(feat);
    k_stats1<<<BP, 256>>>(xyz, rot, W1);
    k_red_a <<<dim3(32,2), 256>>>(0);
    k_red_b <<<1, 256>>>(0, g1, b1);
    k_conv2 <<<BP, 256>>>(xyz, rot, W1);
    k_red_a <<<dim3(32,2), 256>>>(2);
    k_red_b <<<1, 256>>>(1, g2, b2);
    k_final <<<BP/32, 256>>>(out);
}

// round 3
// speedup vs baseline: 2.2018x; 2.2018x over previous
#include <cuda_runtime.h>
#include <cstdint>

#define Bb 4
#define Nn 2048
#define Cc 256
#define OO 256
#define Ss 32
#define BP (Bb*Nn)            // 8192
#define Ee (BP*Ss)            // 262144
#define K1 259

#define HMINf (-0.02f)
#define HMAXf (0.04f)
#define EPSf  (1e-5f)
#define INVCNT (1.0f/(float)Ee)

// ---------------- static device scratch (allocation-free rule) ----------------
__device__ float d_W1fT[Cc*OO];            // W1fT[c][o] = W1[o][3+c]
__device__ float d_W2tf[OO*Cc];            // tf32-rounded W2, row-major [o][c]
__device__ int   d_idx [BP*Ss];            // neighbor indices
__device__ float d_F1  [(size_t)Bb*Nn*OO]; // F1[b][n][o]  (8MB)
__device__ float d_ps1s[BP*OO], d_ps1q[BP*OO];   // stage-1 partial sums
__device__ float d_ps2s[BP*OO], d_ps2q[BP*OO];   // stage-2 partial sums
__device__ float d_mx2 [BP*OO], d_mn2 [BP*OO];   // per-(bp,o) max/min of y2 over s
__device__ float d_pp  [4*32*OO];                // level-2 partials
__device__ float d_scale1[OO], d_shift1[OO];
__device__ float d_scale2[OO], d_shift2[OO];

// ---------------- K0: weight prep ----------------
__global__ void k_wt(const float* __restrict__ W1, const float* __restrict__ W2){
    int i = blockIdx.x*256 + threadIdx.x;      // i = o*256 + c for W2
    int o = i >> 8, c = i & 255;
    d_W1fT[c*OO + o] = W1[o*K1 + 3 + c];
    uint32_t t;
    asm("cvt.rna.tf32.f32 %0, %1;" : "=r"(t) : "f"(W2[i]));
    d_W2tf[i] = __uint_as_float(t);
}

// ---------------- K1: cylinder query (one warp per (b,p)) ----------------
__global__ void k_idx(const float* __restrict__ xyz, const float* __restrict__ rot){
    int bp   = blockIdx.x*8 + (threadIdx.x >> 5);
    int lane = threadIdx.x & 31;
    int b = bp >> 11;
    const float* R = rot + (size_t)bp*9;
    float r00=R[0],r01=R[1],r02=R[2],r10=R[3],r11=R[4],r12=R[5],r20=R[6],r21=R[7],r22=R[8];
    const float* cc = xyz + (size_t)bp*3;
    float cx=cc[0], cy=cc[1], cz=cc[2];
    const float R2v = (float)(0.05*0.05);
    int count = 0, firstn = 0;
    bool have = false;
    for (int base = 0; base < Nn && count < Ss; base += 32){
        int n = base + lane;
        const float* q = xyz + ((size_t)b*Nn + n)*3;
        float dx=q[0]-cx, dy=q[1]-cy, dz=q[2]-cz;
        float a0 = r00*dx + r01*dy + r02*dz;
        float a1 = r10*dx + r11*dy + r12*dz;
        float a2 = r20*dx + r21*dy + r22*dz;
        bool m = (a1*a1 + a2*a2 < R2v) & (a0 > HMINf) & (a0 < HMAXf);
        unsigned bal = __ballot_sync(0xffffffffu, m);
        if (!have && bal){ firstn = base + (__ffs(bal) - 1); have = true; }
        int pre = __popc(bal & ((1u << lane) - 1u));
        if (m && count + pre < Ss) d_idx[bp*Ss + count + pre] = n;
        count += __popc(bal);
    }
    if (count < Ss){
        for (int j = count + lane; j < Ss; j += 32) d_idx[bp*Ss + j] = firstn;
    }
}

// ---------------- K2: F1 = W1_feat @ feat ----------------
__global__ void __launch_bounds__(256) k_F1(const float* __restrict__ feat){
    int b  = blockIdx.y;
    int n0 = blockIdx.x * 32;
    __shared__ __align__(16) float fsh[32][32];
    int tid = threadIdx.x;
    int o = tid;
    float acc[32];
    #pragma unroll
    for (int n = 0; n < 32; n++) acc[n] = 0.f;

    for (int ck = 0; ck < 8; ck++){
        #pragma unroll
        for (int r = 0; r < 4; r++){
            int li = tid + r*256;
            int ci = li >> 5, nj = li & 31;
            fsh[ci][nj] = feat[((size_t)b*Cc + ck*32 + ci)*Nn + n0 + nj];
        }
        __syncthreads();
        #pragma unroll 4
        for (int ci2 = 0; ci2 < 32; ci2++){
            float w = d_W1fT[(ck*32 + ci2)*OO + o];
            const float4* row = reinterpret_cast<const float4*>(&fsh[ci2][0]);
            #pragma unroll
            for (int nq = 0; nq < 8; nq++){
                float4 f = row[nq];
                acc[4*nq+0] = fmaf(f.x, w, acc[4*nq+0]);
                acc[4*nq+1] = fmaf(f.y, w, acc[4*nq+1]);
                acc[4*nq+2] = fmaf(f.z, w, acc[4*nq+2]);
                acc[4*nq+3] = fmaf(f.w, w, acc[4*nq+3]);
            }
        }
        __syncthreads();
    }
    #pragma unroll
    for (int n = 0; n < 32; n++)
        d_F1[((size_t)b*Nn + n0 + n)*OO + o] = acc[n];
}

// ---------------- K3: stats of conv1 output (no materialization) ----------------
__global__ void __launch_bounds__(256) k_stats1(const float* __restrict__ xyz,
                                                const float* __restrict__ rot,
                                                const float* __restrict__ W1){
    int bp = blockIdx.x;
    int b = bp >> 11;
    __shared__ int   idxs[32];
    __shared__ float gx[32], gy[32], gz[32];
    int tid = threadIdx.x;
    if (tid < 32){
        int s = tid;
        int i = d_idx[bp*Ss + s];
        idxs[s] = i;
        const float* R = rot + (size_t)bp*9;
        const float* c = xyz + (size_t)bp*3;
        const float* q = xyz + ((size_t)b*Nn + i)*3;
        float vx = (q[0]-c[0]) / 0.05f;
        float vy = (q[1]-c[1]) / 0.05f;
        float vz = (q[2]-c[2]) / 0.05f;
        gx[s] = vx*R[0] + vy*R[3] + vz*R[6];
        gy[s] = vx*R[1] + vy*R[4] + vz*R[7];
        gz[s] = vx*R[2] + vy*R[5] + vz*R[8];
    }
    __syncthreads();

    int o = tid;
    float w0 = W1[o*K1+0], w1 = W1[o*K1+1], w2 = W1[o*K1+2];
    const float* F1b = d_F1 + (size_t)b*Nn*OO;
    float lsum = 0.f, lsq = 0.f;
    #pragma unroll 4
    for (int s = 0; s < Ss; s++){
        float v = F1b[(size_t)idxs[s]*OO + o];
        v = fmaf(w0, gx[s], fmaf(w1, gy[s], fmaf(w2, gz[s], v)));
        lsum += v;
        lsq  = fmaf(v, v, lsq);
    }
    d_ps1s[bp*OO + o] = lsum;
    d_ps1q[bp*OO + o] = lsq;
}

// ---------------- deterministic two-level reduction ----------------
__global__ void k_red_a(int base){
    int which = base + blockIdx.y;               // 0..3
    const float* src = (which == 0) ? d_ps1s : (which == 1) ? d_ps1q
                     : (which == 2) ? d_ps2s : d_ps2q;
    float* dst = d_pp + which*(32*OO);
    int z = blockIdx.x;                          // 0..31
    int o = threadIdx.x;
    float s = 0.f;
    for (int k = 0; k < 256; k++)
        s += src[((size_t)(z*256 + k))*OO + o];
    dst[z*OO + o] = s;
}

__global__ void k_red_b(int stage, const float* __restrict__ gamma,
                        const float* __restrict__ beta){
    int o = threadIdx.x;
    const float* pps = d_pp + (2*stage + 0)*(32*OO);
    const float* ppq = d_pp + (2*stage + 1)*(32*OO);
    float s = 0.f, q = 0.f;
    for (int z = 0; z < 32; z++){ s += pps[z*OO + o]; q += ppq[z*OO + o]; }
    float mu  = s * INVCNT;
    float var = q * INVCNT - mu*mu;
    float sc  = rsqrtf(var + EPSf) * gamma[o];
    float sf  = beta[o] - mu*sc;
    if (stage == 0){ d_scale1[o] = sc; d_shift1[o] = sf; }
    else           { d_scale2[o] = sc; d_shift2[o] = sf; }
}

// ---------------- tf32 mma helper ----------------
__device__ __forceinline__ void mma_tf32(float& d0, float& d1, float& d2, float& d3,
                                         uint32_t a0, uint32_t a1, uint32_t a2, uint32_t a3,
                                         uint32_t b0, uint32_t b1){
    asm volatile("mma.sync.aligned.m16n8k8.row.col.f32.tf32.tf32.f32 "
                 "{%0,%1,%2,%3}, {%4,%5,%6,%7}, {%8,%9}, {%0,%1,%2,%3};\n"
                 : "+f"(d0), "+f"(d1), "+f"(d2), "+f"(d3)
                 : "r"(a0), "r"(a1), "r"(a2), "r"(a3), "r"(b0), "r"(b1));
}

#define HSTR 260    // h tile row stride (floats), even + conflict-friendly

// ---------------- K4: conv2 on tensor cores, 2 bp per block, stats epilogue ----------------
__global__ void __launch_bounds__(256, 2) k_conv2(const float* __restrict__ xyz,
                                                  const float* __restrict__ rot,
                                                  const float* __restrict__ W1){
    extern __shared__ float smem[];
    float* hbase = smem;                          // [64][HSTR]
    int*   idxs  = (int*)(smem + 64*HSTR);        // [64]
    float* gxx   = smem + 64*HSTR + 64;
    float* gyy   = gxx + 64;
    float* gzz   = gyy + 64;

    int tid = threadIdx.x;
    int bp0 = blockIdx.x * 2;
    int b   = bp0 >> 11;                          // both bp's in same batch (2048 even)

    // --- geometry for 2 bp's ---
    if (tid < 64){
        int s  = tid;
        int bp = bp0 + (s >> 5);
        int i  = d_idx[bp*Ss + (s & 31)];
        idxs[s] = i;
        const float* R = rot + (size_t)bp*9;
        const float* c = xyz + (size_t)bp*3;
        const float* q = xyz + ((size_t)b*Nn + i)*3;
        float vx = (q[0]-c[0]) / 0.05f;
        float vy = (q[1]-c[1]) / 0.05f;
        float vz = (q[2]-c[2]) / 0.05f;
        gxx[s] = vx*R[0] + vy*R[3] + vz*R[6];
        gyy[s] = vx*R[1] + vy*R[4] + vz*R[7];
        gzz[s] = vx*R[2] + vy*R[5] + vz*R[8];
    }
    __syncthreads();

    // --- build h tile: h[s][c] = tf32(relu(BN1(y1))) ---
    {
        int c = tid;
        float w0 = W1[c*K1+0], w1 = W1[c*K1+1], w2 = W1[c*K1+2];
        float sc = d_scale1[c], sf = d_shift1[c];
        const float* F1b = d_F1 + (size_t)b*Nn*OO;
        #pragma unroll 4
        for (int s = 0; s < 64; s++){
            float v = F1b[(size_t)idxs[s]*OO + c];
            v = fmaf(w0, gxx[s], fmaf(w1, gyy[s], fmaf(w2, gzz[s], v)));
            v = fmaxf(fmaf(v, sc, sf), 0.f);
            uint32_t t;
            asm("cvt.rna.tf32.f32 %0, %1;" : "=r"(t) : "f"(v));
            hbase[s*HSTR + c] = __uint_as_float(t);
        }
    }
    __syncthreads();

    // --- tensor-core GEMM: D[o,s] = sum_c W2[o,c] * h[s,c] ---
    // k-slot permutation: slot j<4 -> c = kb+2j ; slot j>=4 -> c = kb+2(j-4)+1
    // so per-thread A/B fragment elements are contiguous float2's.
    int lane = tid & 31, wid = tid >> 5;
    int qq = lane & 3, gid = lane >> 2;
    int obase = wid * 32;

    const float2* pA0 = (const float2*)(d_W2tf + (size_t)(obase + gid     )*Cc);
    const float2* pA1 = (const float2*)(d_W2tf + (size_t)(obase + gid +  8)*Cc);
    const float2* pA2 = (const float2*)(d_W2tf + (size_t)(obase + gid + 16)*Cc);
    const float2* pA3 = (const float2*)(d_W2tf + (size_t)(obase + gid + 24)*Cc);

    const float2* pB[8];
    #pragma unroll
    for (int j = 0; j < 8; j++){
        int srow = 32*(j >> 2) + 8*(j & 3) + gid;
        pB[j] = (const float2*)(hbase + srow*HSTR);
    }

    float acc[2][8][4];
    #pragma unroll
    for (int i = 0; i < 2; i++)
        #pragma unroll
        for (int j = 0; j < 8; j++)
            #pragma unroll
            for (int k = 0; k < 4; k++) acc[i][j][k] = 0.f;

    #pragma unroll 4
    for (int kt = 0; kt < 32; kt++){
        int ko = kt*4 + qq;
        float2 A00 = pA0[ko], A01 = pA1[ko], A10 = pA2[ko], A11 = pA3[ko];
        uint32_t a00x = __float_as_uint(A00.x), a00y = __float_as_uint(A00.y);
        uint32_t a01x = __float_as_uint(A01.x), a01y = __float_as_uint(A01.y);
        uint32_t a10x = __float_as_uint(A10.x), a10y = __float_as_uint(A10.y);
        uint32_t a11x = __float_as_uint(A11.x), a11y = __float_as_uint(A11.y);
        #pragma unroll
        for (int j = 0; j < 8; j++){
            float2 Bv = pB[j][ko];
            uint32_t b0 = __float_as_uint(Bv.x), b1 = __float_as_uint(Bv.y);
            mma_tf32(acc[0][j][0], acc[0][j][1], acc[0][j][2], acc[0][j][3],
                     a00x, a01x, a00y, a01y, b0, b1);
            mma_tf32(acc[1][j][0], acc[1][j][1], acc[1][j][2], acc[1][j][3],
                     a10x, a11x, a10y, a11y, b0, b1);
        }
    }

    // --- epilogue: per-(bp,o) sum / sumsq / max / min over s ---
    #pragma unroll
    for (int half = 0; half < 2; half++){
        int bp = bp0 + half;
        #pragma unroll
        for (int i = 0; i < 2; i++){
            float s0=0.f, q0=0.f, mx0=-3.4e38f, mn0=3.4e38f;
            float s1=0.f, q1=0.f, mx1=-3.4e38f, mn1=3.4e38f;
            #pragma unroll
            for (int j4 = 0; j4 < 4; j4++){
                const float* a = acc[i][half*4 + j4];
                s0 += a[0] + a[1];
                q0  = fmaf(a[0], a[0], fmaf(a[1], a[1], q0));
                mx0 = fmaxf(mx0, fmaxf(a[0], a[1]));
                mn0 = fminf(mn0, fminf(a[0], a[1]));
                s1 += a[2] + a[3];
                q1  = fmaf(a[2], a[2], fmaf(a[3], a[3], q1));
                mx1 = fmaxf(mx1, fmaxf(a[2], a[3]));
                mn1 = fminf(mn1, fminf(a[2], a[3]));
            }
            #pragma unroll
            for (int msk = 1; msk <= 2; msk <<= 1){
                s0 += __shfl_xor_sync(0xffffffffu, s0, msk);
                q0 += __shfl_xor_sync(0xffffffffu, q0, msk);
                mx0 = fmaxf(mx0, __shfl_xor_sync(0xffffffffu, mx0, msk));
                mn0 = fminf(mn0, __shfl_xor_sync(0xffffffffu, mn0, msk));
                s1 += __shfl_xor_sync(0xffffffffu, s1, msk);
                q1 += __shfl_xor_sync(0xffffffffu, q1, msk);
                mx1 = fmaxf(mx1, __shfl_xor_sync(0xffffffffu, mx1, msk));
                mn1 = fminf(mn1, __shfl_xor_sync(0xffffffffu, mn1, msk));
            }
            if (qq == 0){
                int o0 = obase + 16*i + gid;
                size_t ix0 = (size_t)bp*OO + o0;
                d_ps2s[ix0] = s0; d_ps2q[ix0] = q0; d_mx2[ix0] = mx0; d_mn2[ix0] = mn0;
                size_t ix1 = ix0 + 8;
                d_ps2s[ix1] = s1; d_ps2q[ix1] = q1; d_mx2[ix1] = mx1; d_mn2[ix1] = mn1;
            }
        }
    }
}

// ---------------- K5: BN2 + relu + max via monotonicity, transpose-write ----------------
__global__ void __launch_bounds__(256) k_final(float* __restrict__ out){
    int blk = blockIdx.x;                 // 256 blocks, 32 p's each
    int bp0 = blk * 32;
    int b = bp0 >> 11;
    int pbase = bp0 & 2047;
    int tid = threadIdx.x;
    __shared__ float sh[256*33];

    int o = tid;
    float sc = d_scale2[o], sf = d_shift2[o];
    for (int p = 0; p < 32; p++){
        size_t ix = (size_t)(bp0 + p)*OO + o;
        float mx = d_mx2[ix], mn = d_mn2[ix];
        float m = (sc >= 0.f) ? mx : mn;
        sh[o*33 + p] = fmaxf(fmaf(m, sc, sf), 0.f);
    }
    __syncthreads();

    int p   = tid & 31;
    int og0 = (tid >> 5) * 32;
    #pragma unroll
    for (int k = 0; k < 32; k++){
        int o2 = og0 + k;
        out[((size_t)(b*OO + o2))*Nn + pbase + p] = sh[o2*33 + p];
    }
}

// ---------------- launcher ----------------
extern "C" void kernel_launch(void* const* d_in, const int* in_sizes, int n_in,
                              void* d_out, int out_size){
    (void)in_sizes; (void)n_in; (void)out_size;
    const float* xyz  = (const float*)d_in[0];
    const float* feat = (const float*)d_in[1];
    const float* rot  = (const float*)d_in[2];
    const float* W1   = (const float*)d_in[3];
    const float* g1   = (const float*)d_in[4];
    const float* b1   = (const float*)d_in[5];
    const float* W2   = (const float*)d_in[6];
    const float* g2   = (const float*)d_in[7];
    const float* b2   = (const float*)d_in[8];
    float* out = (float*)d_out;

    const int SMEMB = (64*HSTR + 64*4) * 4;   // 67,584 B
    cudaFuncSetAttribute(k_conv2, cudaFuncAttributeMaxDynamicSharedMemorySize, SMEMB);

    k_wt    <<<256, 256>>>(W1, W2);
    k_idx   <<<BP/8, 256>>>(xyz, rot);
    k_F1    <<<dim3(Nn/32, Bb), 256>>>(feat);
    k_stats1<<<BP, 256>>>(xyz, rot, W1);
    k_red_a <<<dim3(32,2), 256>>>(0);
    k_red_b <<<1, 256>>>(0, g1, b1);
    k_conv2 <<<BP/2, 256, SMEMB>>>(xyz, rot, W1);
    k_red_a <<<dim3(32,2), 256>>>(2);
    k_red_b <<<1, 256>>>(1, g2, b2);
    k_final <<<BP/32, 256>>>(out);
}

// round 4
// speedup vs baseline: 2.7372x; 1.2431x over previous
#include <cuda_runtime.h>
#include <cuda_fp16.h>
#include <cstdint>

#define Bb 4
#define Nn 2048
#define Cc 256
#define OO 256
#define Ss 32
#define BP (Bb*Nn)            // 8192
#define Ee (BP*Ss)            // 262144
#define K1 259

#define HMINf (-0.02f)
#define HMAXf (0.04f)
#define EPSf  (1e-5f)
#define INVCNT (1.0f/(float)Ee)

// ---------------- static device scratch (allocation-free rule) ----------------
__device__ float  d_W1fT[Cc*OO];            // W1fT[c][o] = W1[o][3+c]
__device__ __half d_W2h [OO*Cc];            // fp16 W2, k-slot-permuted: [o][p(c)]
__device__ int    d_idx [BP*Ss];            // neighbor indices
__device__ float  d_F1  [(size_t)Bb*Nn*OO]; // F1[b][n][o]  (8MB)
__device__ float  d_ps1s[BP*OO], d_ps1q[BP*OO];   // stage-1 partial sums
__device__ float  d_ps2s[BP*OO], d_ps2q[BP*OO];   // stage-2 partial sums
__device__ float  d_mx2 [BP*OO], d_mn2 [BP*OO];   // per-(bp,o) max/min of y2 over s
__device__ float  d_pp  [4*32*OO];                // level-2 partials
__device__ float  d_scale1[OO], d_shift1[OO];
__device__ float  d_scale2[OO], d_shift2[OO];

// k-slot permutation: position p within a 16-group holds channel c such that
// p = 4q + 2*hi + r  where  c16 = 2q + r + 8*hi.
// Then halfs at positions {16kt+4q .. +3} are channels {2q,2q+1,2q+8,2q+9} of step kt,
// i.e. exactly one thread's A (or B) fragment = one 8-byte load.
__device__ __forceinline__ int kperm(int c){
    int c16 = c & 15;
    int q  = (c16 & 7) >> 1;
    int r  = c16 & 1;
    int hi = (c16 >> 3) & 1;
    return (c & ~15) | (q*4 + hi*2 + r);
}

// ---------------- K0: weight prep ----------------
__global__ void k_wt(const float* __restrict__ W1, const float* __restrict__ W2){
    int i = blockIdx.x*256 + threadIdx.x;      // i = o*256 + c for W2
    int o = i >> 8, c = i & 255;
    d_W1fT[c*OO + o] = W1[o*K1 + 3 + c];
    d_W2h[o*Cc + kperm(c)] = __float2half_rn(W2[i]);
}

// ---------------- K1: cylinder query (one warp per (b,p)) ----------------
__global__ void k_idx(const float* __restrict__ xyz, const float* __restrict__ rot){
    int bp   = blockIdx.x*8 + (threadIdx.x >> 5);
    int lane = threadIdx.x & 31;
    int b = bp >> 11;
    const float* R = rot + (size_t)bp*9;
    float r00=R[0],r01=R[1],r02=R[2],r10=R[3],r11=R[4],r12=R[5],r20=R[6],r21=R[7],r22=R[8];
    const float* cc = xyz + (size_t)bp*3;
    float cx=cc[0], cy=cc[1], cz=cc[2];
    const float R2v = (float)(0.05*0.05);
    int count = 0, firstn = 0;
    bool have = false;
    for (int base = 0; base < Nn && count < Ss; base += 32){
        int n = base + lane;
        const float* q = xyz + ((size_t)b*Nn + n)*3;
        float dx=q[0]-cx, dy=q[1]-cy, dz=q[2]-cz;
        float a0 = r00*dx + r01*dy + r02*dz;
        float a1 = r10*dx + r11*dy + r12*dz;
        float a2 = r20*dx + r21*dy + r22*dz;
        bool m = (a1*a1 + a2*a2 < R2v) & (a0 > HMINf) & (a0 < HMAXf);
        unsigned bal = __ballot_sync(0xffffffffu, m);
        if (!have && bal){ firstn = base + (__ffs(bal) - 1); have = true; }
        int pre = __popc(bal & ((1u << lane) - 1u));
        if (m && count + pre < Ss) d_idx[bp*Ss + count + pre] = n;
        count += __popc(bal);
    }
    if (count < Ss){
        for (int j = count + lane; j < Ss; j += 32) d_idx[bp*Ss + j] = firstn;
    }
}

// ---------------- K2: F1 = W1_feat @ feat ----------------
__global__ void __launch_bounds__(256) k_F1(const float* __restrict__ feat){
    int b  = blockIdx.y;
    int n0 = blockIdx.x * 32;
    __shared__ __align__(16) float fsh[32][32];
    int tid = threadIdx.x;
    int o = tid;
    float acc[32];
    #pragma unroll
    for (int n = 0; n < 32; n++) acc[n] = 0.f;

    for (int ck = 0; ck < 8; ck++){
        #pragma unroll
        for (int r = 0; r < 4; r++){
            int li = tid + r*256;
            int ci = li >> 5, nj = li & 31;
            fsh[ci][nj] = feat[((size_t)b*Cc + ck*32 + ci)*Nn + n0 + nj];
        }
        __syncthreads();
        #pragma unroll 4
        for (int ci2 = 0; ci2 < 32; ci2++){
            float w = d_W1fT[(ck*32 + ci2)*OO + o];
            const float4* row = reinterpret_cast<const float4*>(&fsh[ci2][0]);
            #pragma unroll
            for (int nq = 0; nq < 8; nq++){
                float4 f = row[nq];
                acc[4*nq+0] = fmaf(f.x, w, acc[4*nq+0]);
                acc[4*nq+1] = fmaf(f.y, w, acc[4*nq+1]);
                acc[4*nq+2] = fmaf(f.z, w, acc[4*nq+2]);
                acc[4*nq+3] = fmaf(f.w, w, acc[4*nq+3]);
            }
        }
        __syncthreads();
    }
    #pragma unroll
    for (int n = 0; n < 32; n++)
        d_F1[((size_t)b*Nn + n0 + n)*OO + o] = acc[n];
}

// ---------------- K3: stats of conv1 output (no materialization) ----------------
__global__ void __launch_bounds__(256) k_stats1(const float* __restrict__ xyz,
                                                const float* __restrict__ rot,
                                                const float* __restrict__ W1){
    int bp = blockIdx.x;
    int b = bp >> 11;
    __shared__ int   idxs[32];
    __shared__ float gx[32], gy[32], gz[32];
    int tid = threadIdx.x;
    if (tid < 32){
        int s = tid;
        int i = d_idx[bp*Ss + s];
        idxs[s] = i;
        const float* R = rot + (size_t)bp*9;
        const float* c = xyz + (size_t)bp*3;
        const float* q = xyz + ((size_t)b*Nn + i)*3;
        float vx = (q[0]-c[0]) / 0.05f;
        float vy = (q[1]-c[1]) / 0.05f;
        float vz = (q[2]-c[2]) / 0.05f;
        gx[s] = vx*R[0] + vy*R[3] + vz*R[6];
        gy[s] = vx*R[1] + vy*R[4] + vz*R[7];
        gz[s] = vx*R[2] + vy*R[5] + vz*R[8];
    }
    __syncthreads();

    int o = tid;
    float w0 = W1[o*K1+0], w1 = W1[o*K1+1], w2 = W1[o*K1+2];
    const float* F1b = d_F1 + (size_t)b*Nn*OO;
    float lsum = 0.f, lsq = 0.f;
    #pragma unroll 4
    for (int s = 0; s < Ss; s++){
        float v = F1b[(size_t)idxs[s]*OO + o];
        v = fmaf(w0, gx[s], fmaf(w1, gy[s], fmaf(w2, gz[s], v)));
        lsum += v;
        lsq  = fmaf(v, v, lsq);
    }
    d_ps1s[bp*OO + o] = lsum;
    d_ps1q[bp*OO + o] = lsq;
}

// ---------------- deterministic two-level reduction ----------------
__global__ void k_red_a(int base){
    int which = base + blockIdx.y;               // 0..3
    const float* src = (which == 0) ? d_ps1s : (which == 1) ? d_ps1q
                     : (which == 2) ? d_ps2s : d_ps2q;
    float* dst = d_pp + which*(32*OO);
    int z = blockIdx.x;                          // 0..31
    int o = threadIdx.x;
    float s = 0.f;
    for (int k = 0; k < 256; k++)
        s += src[((size_t)(z*256 + k))*OO + o];
    dst[z*OO + o] = s;
}

__global__ void k_red_b(int stage, const float* __restrict__ gamma,
                        const float* __restrict__ beta){
    int o = threadIdx.x;
    const float* pps = d_pp + (2*stage + 0)*(32*OO);
    const float* ppq = d_pp + (2*stage + 1)*(32*OO);
    float s = 0.f, q = 0.f;
    for (int z = 0; z < 32; z++){ s += pps[z*OO + o]; q += ppq[z*OO + o]; }
    float mu  = s * INVCNT;
    float var = q * INVCNT - mu*mu;
    float sc  = rsqrtf(var + EPSf) * gamma[o];
    float sf  = beta[o] - mu*sc;
    if (stage == 0){ d_scale1[o] = sc; d_shift1[o] = sf; }
    else           { d_scale2[o] = sc; d_shift2[o] = sf; }
}

// ---------------- fp16 mma helper ----------------
__device__ __forceinline__ void mma_f16(float& d0, float& d1, float& d2, float& d3,
                                        uint32_t a0, uint32_t a1, uint32_t a2, uint32_t a3,
                                        uint32_t b0, uint32_t b1){
    asm volatile("mma.sync.aligned.m16n8k16.row.col.f32.f16.f16.f32 "
                 "{%0,%1,%2,%3}, {%4,%5,%6,%7}, {%8,%9}, {%0,%1,%2,%3};\n"
                 : "+f"(d0), "+f"(d1), "+f"(d2), "+f"(d3)
                 : "r"(a0), "r"(a1), "r"(a2), "r"(a3), "r"(b0), "r"(b1));
}

#define HSTR 272    // h tile row stride in halfs: 272 words%... gives 2-per-bank LDS.64 (optimal)

// ---------------- K4: conv2, fp16 tensor cores, 4 bp per block, stats epilogue ----------------
__global__ void __launch_bounds__(512, 1) k_conv2(const float* __restrict__ xyz,
                                                  const float* __restrict__ rot,
                                                  const float* __restrict__ W1){
    extern __shared__ __align__(16) char smraw[];
    __half* h16  = (__half*)smraw;                       // [128][HSTR]
    int*    idxs = (int*)(smraw + 128*HSTR*2);           // [128]
    float*  gxx  = (float*)(idxs + 128);
    float*  gyy  = gxx + 128;
    float*  gzz  = gyy + 128;

    int tid = threadIdx.x;
    int bp0 = blockIdx.x * 4;                            // 4 bp per block, same batch
    int b   = bp0 >> 11;

    // --- geometry for 4 bp's (128 samples) ---
    if (tid < 128){
        int s  = tid;
        int bp = bp0 + (s >> 5);
        int i  = d_idx[bp*Ss + (s & 31)];
        idxs[s] = i;
        const float* R = rot + (size_t)bp*9;
        const float* c = xyz + (size_t)bp*3;
        const float* q = xyz + ((size_t)b*Nn + i)*3;
        float vx = (q[0]-c[0]) / 0.05f;
        float vy = (q[1]-c[1]) / 0.05f;
        float vz = (q[2]-c[2]) / 0.05f;
        gxx[s] = vx*R[0] + vy*R[3] + vz*R[6];
        gyy[s] = vx*R[1] + vy*R[4] + vz*R[7];
        gzz[s] = vx*R[2] + vy*R[5] + vz*R[8];
    }
    __syncthreads();

    // --- build h tile: h[s][kperm(c)] = fp16(relu(BN1(y1))) ---
    {
        int c     = tid & 255;
        int sbase = (tid >> 8) * 64;
        int p     = kperm(c);
        float w0 = W1[c*K1+0], w1 = W1[c*K1+1], w2 = W1[c*K1+2];
        float sc = d_scale1[c], sf = d_shift1[c];
        const float* F1b = d_F1 + (size_t)b*Nn*OO;
        #pragma unroll 8
        for (int ds = 0; ds < 64; ds++){
            int s = sbase + ds;
            float v = F1b[(size_t)idxs[s]*OO + c];
            v = fmaf(w0, gxx[s], fmaf(w1, gyy[s], fmaf(w2, gzz[s], v)));
            v = fmaxf(fmaf(v, sc, sf), 0.f);
            h16[s*HSTR + p] = __float2half_rn(v);
        }
    }
    __syncthreads();

    // --- tensor-core GEMM: D[o,s] = sum_c W2[o,c] * h[s,c] ---
    int lane = tid & 31, w = tid >> 5;
    int q = lane & 3, g = lane >> 2;
    int obase = (w & 7) * 32;                    // 8 warps cover 256 o
    int warpS = (w >> 3) * 64;                   // 2 warp-rows cover 128 s

    // A: 4 o-rows per thread, 8B (4 halfs) per row per kt
    const uint2* A0 = (const uint2*)(d_W2h + (size_t)(obase + g     )*Cc);
    const uint2* A1 = (const uint2*)(d_W2h + (size_t)(obase + g +  8)*Cc);
    const uint2* A2 = (const uint2*)(d_W2h + (size_t)(obase + g + 16)*Cc);
    const uint2* A3 = (const uint2*)(d_W2h + (size_t)(obase + g + 24)*Cc);

    const uint2* Bp[8];
    #pragma unroll
    for (int j = 0; j < 8; j++)
        Bp[j] = (const uint2*)(h16 + (size_t)(warpS + 8*j + g)*HSTR);

    float acc[2][8][4];
    #pragma unroll
    for (int i = 0; i < 2; i++)
        #pragma unroll
        for (int j = 0; j < 8; j++)
            #pragma unroll
            for (int k = 0; k < 4; k++) acc[i][j][k] = 0.f;

    #pragma unroll 2
    for (int kt = 0; kt < 16; kt++){
        int ko = kt*4 + q;
        uint2 a0 = A0[ko], a1 = A1[ko], a2 = A2[ko], a3 = A3[ko];
        #pragma unroll
        for (int j = 0; j < 8; j++){
            uint2 bv = Bp[j][ko];
            mma_f16(acc[0][j][0], acc[0][j][1], acc[0][j][2], acc[0][j][3],
                    a0.x, a1.x, a0.y, a1.y, bv.x, bv.y);
            mma_f16(acc[1][j][0], acc[1][j][1], acc[1][j][2], acc[1][j][3],
                    a2.x, a3.x, a2.y, a3.y, bv.x, bv.y);
        }
    }

    // --- epilogue: per-(bp,o) sum / sumsq / max / min over that bp's 32 s ---
    // n-tile j<4 -> first bp of warp's 64-s range; j>=4 -> second.
    #pragma unroll
    for (int half = 0; half < 2; half++){
        int bp = bp0 + 2*(w >> 3) + half;
        #pragma unroll
        for (int i = 0; i < 2; i++){
            float s0=0.f, q0=0.f, mx0=-3.4e38f, mn0=3.4e38f;   // row g
            float s1=0.f, q1=0.f, mx1=-3.4e38f, mn1=3.4e38f;   // row g+8
            #pragma unroll
            for (int j4 = 0; j4 < 4; j4++){
                const float* a = acc[i][half*4 + j4];
                s0 += a[0] + a[1];
                q0  = fmaf(a[0], a[0], fmaf(a[1], a[1], q0));
                mx0 = fmaxf(mx0, fmaxf(a[0], a[1]));
                mn0 = fminf(mn0, fminf(a[0], a[1]));
                s1 += a[2] + a[3];
                q1  = fmaf(a[2], a[2], fmaf(a[3], a[3], q1));
                mx1 = fmaxf(mx1, fmaxf(a[2], a[3]));
                mn1 = fminf(mn1, fminf(a[2], a[3]));
            }
            #pragma unroll
            for (int msk = 1; msk <= 2; msk <<= 1){
                s0 += __shfl_xor_sync(0xffffffffu, s0, msk);
                q0 += __shfl_xor_sync(0xffffffffu, q0, msk);
                mx0 = fmaxf(mx0, __shfl_xor_sync(0xffffffffu, mx0, msk));
                mn0 = fminf(mn0, __shfl_xor_sync(0xffffffffu, mn0, msk));
                s1 += __shfl_xor_sync(0xffffffffu, s1, msk);
                q1 += __shfl_xor_sync(0xffffffffu, q1, msk);
                mx1 = fmaxf(mx1, __shfl_xor_sync(0xffffffffu, mx1, msk));
                mn1 = fminf(mn1, __shfl_xor_sync(0xffffffffu, mn1, msk));
            }
            if (q == 0){
                int o0 = obase + 16*i + g;
                size_t ix0 = (size_t)bp*OO + o0;
                d_ps2s[ix0] = s0; d_ps2q[ix0] = q0; d_mx2[ix0] = mx0; d_mn2[ix0] = mn0;
                size_t ix1 = ix0 + 8;
                d_ps2s[ix1] = s1; d_ps2q[ix1] = q1; d_mx2[ix1] = mx1; d_mn2[ix1] = mn1;
            }
        }
    }
}

// ---------------- K5: BN2 + relu + max via monotonicity, transpose-write ----------------
__global__ void __launch_bounds__(256) k_final(float* __restrict__ out){
    int blk = blockIdx.x;                 // 256 blocks, 32 p's each
    int bp0 = blk * 32;
    int b = bp0 >> 11;
    int pbase = bp0 & 2047;
    int tid = threadIdx.x;
    __shared__ float sh[256*33];

    int o = tid;
    float sc = d_scale2[o], sf = d_shift2[o];
    for (int p = 0; p < 32; p++){
        size_t ix = (size_t)(bp0 + p)*OO + o;
        float mx = d_mx2[ix], mn = d_mn2[ix];
        float m = (sc >= 0.f) ? mx : mn;
        sh[o*33 + p] = fmaxf(fmaf(m, sc, sf), 0.f);
    }
    __syncthreads();

    int p   = tid & 31;
    int og0 = (tid >> 5) * 32;
    #pragma unroll
    for (int k = 0; k < 32; k++){
        int o2 = og0 + k;
        out[((size_t)(b*OO + o2))*Nn + pbase + p] = sh[o2*33 + p];
    }
}

// ---------------- launcher ----------------
extern "C" void kernel_launch(void* const* d_in, const int* in_sizes, int n_in,
                              void* d_out, int out_size){
    (void)in_sizes; (void)n_in; (void)out_size;
    const float* xyz  = (const float*)d_in[0];
    const float* feat = (const float*)d_in[1];
    const float* rot  = (const float*)d_in[2];
    const float* W1   = (const float*)d_in[3];
    const float* g1   = (const float*)d_in[4];
    const float* b1   = (const float*)d_in[5];
    const float* W2   = (const float*)d_in[6];
    const float* g2   = (const float*)d_in[7];
    const float* b2   = (const float*)d_in[8];
    float* out = (float*)d_out;

    const int SMEMB = 128*HSTR*2 + 128*4*4;   // 69632 + 2048 = 71680 B
    cudaFuncSetAttribute(k_conv2, cudaFuncAttributeMaxDynamicSharedMemorySize, SMEMB);

    k_wt    <<<256, 256>>>(W1, W2);
    k_idx   <<<BP/8, 256>>>(xyz, rot);
    k_F1    <<<dim3(Nn/32, Bb), 256>>>(feat);
    k_stats1<<<BP, 256>>>(xyz, rot, W1);
    k_red_a <<<dim3(32,2), 256>>>(0);
    k_red_b <<<1, 256>>>(0, g1, b1);
    k_conv2 <<<BP/4, 512, SMEMB>>>(xyz, rot, W1);
    k_red_a <<<dim3(32,2), 256>>>(2);
    k_red_b <<<1, 256>>>(1, g2, b2);
    k_final <<<BP/32, 256>>>(out);
}